// round 17
// baseline (speedup 1.0000x reference)
#include <cuda_runtime.h>
#include <cuda_bf16.h>
#include <math.h>

#define Bn 512
#define Sn 128
#define Vn 1024
#define NPART 10
#define FULL 0xffffffffu

// Scratch (no allocations allowed)
__device__ __align__(16) float g_ce[Bn * Sn];
__device__ __align__(16) int   g_pred[Bn * Sn];
__device__ __align__(16) float g_part[Bn * NPART];

__device__ __forceinline__ float warpSum(float v) {
#pragma unroll
    for (int off = 16; off > 0; off >>= 1)
        v += __shfl_down_sync(FULL, v, off);
    return v;
}

// ---------------------------------------------------------------------------
// Kernel 1: per-(b,s) log-softmax stats, single pass, one warp per row.
// 4 independent accumulator chains (one per float4 lane) to break the
// serialized FSETP->SEL argmax dependency and FADD chains.
// ---------------------------------------------------------------------------
__global__ __launch_bounds__(256) void dae_k1(const float* __restrict__ logits,
                                              const int*   __restrict__ tgt) {
    int gw   = (int)((blockIdx.x * blockDim.x + threadIdx.x) >> 5);
    int lane = threadIdx.x & 31;

    const float*  row  = logits + (size_t)gw * Vn;
    const float4* row4 = reinterpret_cast<const float4*>(row);

    // prefetch target + target logit early (independent of the reduction)
    int   t  = 0;
    float xt = 0.0f;
    if (lane == 0) {
        t  = __ldg(tgt + gw);
        xt = __ldg(row + t);
    }

    float4 v[8];
#pragma unroll
    for (int k = 0; k < 8; k++) v[k] = __ldcs(row4 + lane + 32 * k);  // evict-first

    int base = lane << 2;

    // 4 independent chains, one per component j
    float mx0 = -3.402823466e38f, mx1 = mx0, mx2 = mx0, mx3 = mx0;
    int   mi0 = 0, mi1 = 0, mi2 = 0, mi3 = 0;
    float sx0 = 0.f, sx1 = 0.f, sx2 = 0.f, sx3 = 0.f;
    float se0 = 0.f, se1 = 0.f, se2 = 0.f, se3 = 0.f;

#pragma unroll
    for (int k = 0; k < 8; k++) {
        int ib = base + (k << 7);
        float x0 = v[k].x, x1 = v[k].y, x2 = v[k].z, x3 = v[k].w;
        sx0 += x0; sx1 += x1; sx2 += x2; sx3 += x3;
        se0 += __expf(x0); se1 += __expf(x1);
        se2 += __expf(x2); se3 += __expf(x3);
        if (x0 > mx0) { mx0 = x0; mi0 = ib; }
        if (x1 > mx1) { mx1 = x1; mi1 = ib + 1; }
        if (x2 > mx2) { mx2 = x2; mi2 = ib + 2; }
        if (x3 > mx3) { mx3 = x3; mi3 = ib + 3; }
    }

    // merge 4 chains (first-occurrence: strict >, tie -> smaller global index)
    float sx = (sx0 + sx1) + (sx2 + sx3);
    float se = (se0 + se1) + (se2 + se3);
    if (mx1 > mx0 || (mx1 == mx0 && mi1 < mi0)) { mx0 = mx1; mi0 = mi1; }
    if (mx3 > mx2 || (mx3 == mx2 && mi3 < mi2)) { mx2 = mx3; mi2 = mi3; }
    if (mx2 > mx0 || (mx2 == mx0 && mi2 < mi0)) { mx0 = mx2; mi0 = mi2; }
    float mx = mx0;
    int   mi = mi0;

#pragma unroll
    for (int off = 16; off > 0; off >>= 1) {
        float om = __shfl_down_sync(FULL, mx, off);
        int   oi = __shfl_down_sync(FULL, mi, off);
        sx += __shfl_down_sync(FULL, sx, off);
        se += __shfl_down_sync(FULL, se, off);
        if (om > mx || (om == mx && oi < mi)) { mx = om; mi = oi; }
    }

    if (lane == 0) {
        float cev = 0.0f;
        if (t != 0) {
            float lse = __logf(se);
            cev = 0.9f * (lse - xt) + 0.1f * (lse - sx * (1.0f / (float)Vn));
        }
        g_ce[gw]   = cev;
        g_pred[gw] = mi;
    }
#if __CUDA_ARCH__ >= 900
    cudaTriggerProgrammaticLaunchCompletion();   // let PDL-dependent K2 sync early
#endif
}

// ---------------------------------------------------------------------------
// Kernel 2: one warp per batch row b, ONE BLOCK each (grid=512, block=32).
// PDL: starts during K1 drain, preloads tgt, waits before touching K1 output.
// ---------------------------------------------------------------------------
__global__ __launch_bounds__(32) void dae_k2(const int* __restrict__ tgt) {
    int b    = (int)blockIdx.x;
    int lane = threadIdx.x;

    // tgt is an input tensor — load before the dependency sync
    int4 tv = __ldg(reinterpret_cast<const int4*>(tgt + b * Sn) + lane);

#if __CUDA_ARCH__ >= 900
    cudaGridDependencySynchronize();             // wait for K1's g_ce/g_pred
#endif

    int4   pv = __ldg(reinterpret_cast<const int4*>(g_pred + b * Sn) + lane);
    float4 cv = __ldg(reinterpret_cast<const float4*>(g_ce + b * Sn) + lane);

    int ts[4] = {tv.x, tv.y, tv.z, tv.w};
    int ps[4] = {pv.x, pv.y, pv.z, pv.w};
    float cs[4] = {cv.x, cv.y, cv.z, cv.w};

    // neighbors from lane+1 (elements 0 and 1); lane 31's garbage is unused
    int tn0 = __shfl_down_sync(FULL, ts[0], 1);
    int tn1 = __shfl_down_sync(FULL, ts[1], 1);
    int pn0 = __shfl_down_sync(FULL, ps[0], 1);
    int pn1 = __shfl_down_sync(FULL, ps[1], 1);

    int padc = (ts[0] != 0) + (ts[1] != 0) + (ts[2] != 0) + (ts[3] != 0);
    int prdc = (ps[0] != 0) + (ps[1] != 0) + (ps[2] != 0) + (ps[3] != 0);
    int L  = __reduce_add_sync(FULL, padc);          // tgt_len
    int PL = __reduce_add_sync(FULL, prdc);          // pred_len

    float rLden = 1.0f / (float)((L > 1) ? L : 1);

    float cw = 0.0f, wsum = 0.0f, corr = 0.0f, bi = 0.0f, tri = 0.0f;
    int vcnt = 0, ecnt = 0;
#pragma unroll
    for (int j = 0; j < 4; j++) {
        int s = (lane << 2) + j;
        float w = (s < L) ? fmaf((float)s * rLden, 0.5f, 1.0f) : 1.0f;
        if (s == L - 3 && L >= 3) w = 1.8f;
        if (s == L - 2 && L >= 2) w = 2.4f;
        if (s == L - 1 && L >= 1) w = 3.0f;
        cw   += cs[j] * w;
        wsum += w;
        int same = (ps[j] == ts[j]);
        corr += (same && ts[j] != 0) ? 1.0f : 0.0f;
        if (s < Sn - 2 && ts[j] != 0) vcnt++;
        if (s == L - 1 && same) ecnt++;              // end-char hit (s==L-1 implies L>0)

        if (s < Sn - 1) {
            int t1 = (j < 3) ? ts[j + 1] : tn0;
            int p1 = (j < 3) ? ps[j + 1] : pn0;
            int pe = (ps[j] == p1);
            int te = (ts[j] == t1);
            bi += (float)pe + (float)te - 2.0f * (float)(pe & te & same);
            if (s < Sn - 2) {
                int t2 = (j < 2) ? ts[j + 2] : ((j == 2) ? tn0 : tn1);
                int p2 = (j < 2) ? ps[j + 2] : ((j == 2) ? pn0 : pn1);
                int pe3 = pe & (p1 == p2);
                int te3 = te & (t1 == t2);
                tri += (float)pe3 + (float)te3 - 2.0f * (float)(pe3 & te3 & same);
            }
        }
    }

    cw   = warpSum(cw);
    wsum = warpSum(wsum);
    corr = warpSum(corr);
    bi   = warpSum(bi);
    tri  = warpSum(tri);
    int vany = __reduce_add_sync(FULL, vcnt);
    int eok  = __reduce_add_sync(FULL, ecnt);

    if (lane == 0) {
        float* pr = g_part + b * NPART;
        pr[0] = cw;
        pr[1] = wsum;
        pr[2] = fabsf((float)(PL - L));
        pr[3] = corr;
        pr[4] = (float)L;
        pr[5] = (float)eok;
        pr[6] = (L == PL) ? 1.0f : 0.0f;
        pr[7] = bi;
        pr[8] = tri;
        pr[9] = (vany > 0) ? 1.0f : 0.0f;
    }
#if __CUDA_ARCH__ >= 900
    cudaTriggerProgrammaticLaunchCompletion();
#endif
}

// ---------------------------------------------------------------------------
// Kernel 3: final reduce over 512 rows of partials -> 4 scalars (PDL after K2).
// ---------------------------------------------------------------------------
__global__ __launch_bounds__(256) void dae_k3(float* __restrict__ dout) {
    int warp = threadIdx.x >> 5;
    int lane = threadIdx.x & 31;

    __shared__ float stot[NPART];

#if __CUDA_ARCH__ >= 900
    cudaGridDependencySynchronize();             // wait for K2's g_part
#endif

#pragma unroll
    for (int rep = 0; rep < 2; rep++) {
        int i = warp + rep * 8;
        if (i < NPART) {
            float v = 0.0f;
#pragma unroll
            for (int k = 0; k < Bn / 32; k++)
                v += g_part[(lane + 32 * k) * NPART + i];
            v = warpSum(v);
            if (lane == 0) stot[i] = v;
        }
    }
    __syncthreads();

    if (threadIdx.x == 0) {
        float weighted_loss  = stot[0] / stot[1];
        float length_penalty = 0.1f * (stot[2] / (float)Bn);
        float bigram_mse = stot[7] / (float)(Bn * (Sn - 1) * Vn);
        float tri_mse    = stot[8] / (float)(Bn * (Sn - 2) * Vn);
        float char_ngram = bigram_mse + ((stot[9] > 0.0f) ? tri_mse : 0.0f);

        dout[0] = weighted_loss + length_penalty + 0.2f * char_ngram;
        dout[1] = (stot[4] > 0.0f) ? (stot[3] / stot[4]) : 0.0f;  // char_acc
        dout[2] = stot[5] / (float)Bn;                            // end_char_acc
        dout[3] = stot[6] / (float)Bn;                            // length_acc
    }
}

// ---------------------------------------------------------------------------
extern "C" void kernel_launch(void* const* d_in, const int* in_sizes, int n_in,
                              void* d_out, int out_size) {
    const float* logits = (const float*)d_in[0];   // (B, S, V) float32
    const int*   tgt    = (const int*)d_in[1];     // (B, S) int32
    float*       res    = (float*)d_out;           // 4 scalars

    dae_k1<<<(Bn * Sn) / 8, 256>>>(logits, tgt);   // one warp per (b,s) row

    // K2 and K3 with programmatic dependent launch (overlap launch with drain)
    cudaLaunchAttribute attr[1];
    attr[0].id = cudaLaunchAttributeProgrammaticStreamSerialization;
    attr[0].val.programmaticStreamSerializationAllowed = 1;

    cudaLaunchConfig_t cfg2 = {};
    cfg2.gridDim  = dim3(Bn, 1, 1);
    cfg2.blockDim = dim3(32, 1, 1);
    cfg2.attrs    = attr;
    cfg2.numAttrs = 1;
    cudaLaunchKernelEx(&cfg2, dae_k2, tgt);

    cudaLaunchConfig_t cfg3 = {};
    cfg3.gridDim  = dim3(1, 1, 1);
    cfg3.blockDim = dim3(256, 1, 1);
    cfg3.attrs    = attr;
    cfg3.numAttrs = 1;
    cudaLaunchKernelEx(&cfg3, dae_k3, res);
}